// round 7
// baseline (speedup 1.0000x reference)
#include <cuda_runtime.h>

#define NN 100000
#define NE 3200000
#define H  64
#define SCAN_B 1024
#define NB ((NN + SCAN_B - 1) / SCAN_B)   // 98

// -------- device scratch (no allocations allowed) --------
__device__ int   g_cnt[NN];
__device__ int   g_row[NN + 1];
__device__ int   g_pos[NN];
__device__ float g_dis[NN];
__device__ int   g_bsum[NB];
__device__ int   g_cs[NE];        // CSR: src node per slot
__device__ float g_cw[NE];        // CSR: dis[s]*dis[d] per slot
__device__ float g_h  [NN * H];   // h1 node features
__device__ float g_P  [NN * H];   // h2 @ Wm1[0:64] + bm1
__device__ float g_Q  [NN * H];   // h2 @ Wm1[64:128]

// -------- CSR build --------
__global__ void k_zero_cnt() {
    int i = blockIdx.x * blockDim.x + threadIdx.x;
    if (i < NN) g_cnt[i] = 0;
}

__global__ void k_hist(const int* __restrict__ dst) {
    int e = blockIdx.x * blockDim.x + threadIdx.x;
    if (e < NE) atomicAdd(&g_cnt[dst[e]], 1);
}

// pass 1: per-block scan, local exclusive into g_row, block sum out
__global__ void k_scan1() {
    __shared__ int ss[SCAN_B];
    int tid = threadIdx.x;
    int i = blockIdx.x * SCAN_B + tid;
    int v = (i < NN) ? g_cnt[i] : 0;
    ss[tid] = v;
    __syncthreads();
#pragma unroll
    for (int off = 1; off < SCAN_B; off <<= 1) {
        int t = (tid >= off) ? ss[tid - off] : 0;
        __syncthreads();
        ss[tid] += t;
        __syncthreads();
    }
    if (i < NN) g_row[i] = ss[tid] - v;
    if (tid == SCAN_B - 1) g_bsum[blockIdx.x] = ss[tid];
}

// pass 2 (fused): each block reduces the preceding block-sums itself,
// adds offset, fuses dis = rsqrt(deg), row[NN] = NE
__global__ void k_scan3() {
    __shared__ int ss[128];
    int tid = threadIdx.x;
    if (tid < 128) ss[tid] = (tid < NB && tid < blockIdx.x) ? g_bsum[tid] : 0;
    __syncthreads();
#pragma unroll
    for (int off = 64; off >= 1; off >>= 1) {
        if (tid < off) ss[tid] += ss[tid + off];
        __syncthreads();
    }
    int base = ss[0];
    int i = blockIdx.x * SCAN_B + tid;
    if (i < NN) {
        int r = g_row[i] + base;
        g_row[i] = r;
        g_pos[i] = r;
        g_dis[i] = rsqrtf((float)(g_cnt[i] + 1));   // +1 self-loop
    }
    if (i == 0) g_row[NN] = NE;
}

__global__ void k_place(const int* __restrict__ src, const int* __restrict__ dst) {
    int e = blockIdx.x * blockDim.x + threadIdx.x;
    if (e >= NE) return;
    int s = src[e], d = dst[e];
    int idx = atomicAdd(&g_pos[d], 1);
    g_cs[idx] = s;
    g_cw[idx] = g_dis[s] * g_dis[d];
}

// -------- fused layer 1: warp per node --------
// ax = sum_edges w*x[s] + dis^2*x[n] (4-dim), then h1 = relu(ax@W1 + b1)
__global__ void k_aggx_h1(const float* __restrict__ x,
                          const float* __restrict__ W1, const float* __restrict__ b1) {
    int w = (blockIdx.x * blockDim.x + threadIdx.x) >> 5;
    if (w >= NN) return;
    int lane = threadIdx.x & 31;
    int r0 = g_row[w], r1 = g_row[w + 1];
    float ax = 0.f, ay = 0.f, az = 0.f, aw = 0.f;
#pragma unroll 4
    for (int r = r0 + lane; r < r1; r += 32) {
        int s = g_cs[r];
        float ww = g_cw[r];
        float4 xv = *reinterpret_cast<const float4*>(x + (size_t)s * 4);
        ax += xv.x * ww; ay += xv.y * ww; az += xv.z * ww; aw += xv.w * ww;
    }
    if (lane == 0) {                     // self-loop term, once
        float dd = g_dis[w]; dd *= dd;
        float4 xv = *reinterpret_cast<const float4*>(x + (size_t)w * 4);
        ax += dd * xv.x; ay += dd * xv.y; az += dd * xv.z; aw += dd * xv.w;
    }
#pragma unroll
    for (int off = 16; off >= 1; off >>= 1) {   // xor: all lanes end with total
        ax += __shfl_xor_sync(0xffffffffu, ax, off);
        ay += __shfl_xor_sync(0xffffffffu, ay, off);
        az += __shfl_xor_sync(0xffffffffu, az, off);
        aw += __shfl_xor_sync(0xffffffffu, aw, off);
    }
    size_t o = (size_t)w * H;
#pragma unroll
    for (int half = 0; half < 2; half++) {
        int c = lane + half * 32;
        float s = ax * __ldg(W1 + c) + ay * __ldg(W1 + 64 + c)
                + az * __ldg(W1 + 128 + c) + aw * __ldg(W1 + 192 + c) + __ldg(b1 + c);
        g_h[o + c] = fmaxf(s, 0.f);
    }
}

// -------- fused layer 2 + edge-MLP node factor --------
// Block: 512 thr = 16 warps = 16 nodes. Warp aggregates its node's in-edges
// (tmp = sum w*h1[s] + dis^2*h1[n]) straight into smem, then the block runs:
// h2 = relu(tmp@W2+b2) (smem only), P = h2@Wm1[:64]+bm1, Q = h2@Wm1[64:128].
__global__ void k_agg_dense2(const float* __restrict__ W2, const float* __restrict__ b2,
                             const float* __restrict__ Wm1, const float* __restrict__ bm1) {
    __shared__ float sbuf[9216];      // 4096 Wa | 4096 Wb | 1024 node tile
    float* sWa = sbuf;
    float* sWb = sbuf + 4096;
    float* sIn = sbuf + 8192;
    int tid  = threadIdx.x;
    int nb   = blockIdx.x * 16;
    int wid  = tid >> 5, lane = tid & 31;

    // ---- stage A: warp-per-node aggregation, 4-edge unrolled ----
    {
        int node = nb + wid;
        const float2* hp = reinterpret_cast<const float2*>(g_h);
        int r = g_row[node], r1 = g_row[node + 1];
        float a0 = 0.f, a1 = 0.f;
        for (; r + 3 < r1; r += 4) {
            int   s0 = g_cs[r],     s1 = g_cs[r + 1], s2 = g_cs[r + 2], s3 = g_cs[r + 3];
            float w0 = g_cw[r],     w1 = g_cw[r + 1], w2 = g_cw[r + 2], w3 = g_cw[r + 3];
            float2 v0 = hp[(size_t)s0 * 32 + lane];
            float2 v1 = hp[(size_t)s1 * 32 + lane];
            float2 v2 = hp[(size_t)s2 * 32 + lane];
            float2 v3 = hp[(size_t)s3 * 32 + lane];
            a0 += v0.x * w0; a1 += v0.y * w0;
            a0 += v1.x * w1; a1 += v1.y * w1;
            a0 += v2.x * w2; a1 += v2.y * w2;
            a0 += v3.x * w3; a1 += v3.y * w3;
        }
        for (; r < r1; r++) {
            int s = g_cs[r]; float ww = g_cw[r];
            float2 v = hp[(size_t)s * 32 + lane];
            a0 += v.x * ww; a1 += v.y * ww;
        }
        float dd = g_dis[node]; dd *= dd;
        float2 v = hp[(size_t)node * 32 + lane];
        a0 += v.x * dd; a1 += v.y * dd;
        sIn[wid * 64 + 2 * lane]     = a0;
        sIn[wid * 64 + 2 * lane + 1] = a1;
    }
    for (int i = tid; i < 4096; i += 512) sWa[i] = W2[i];
    __syncthreads();

    // ---- stage B: h2 = relu(tmp@W2 + b2), kept in registers ----
    int col = tid & 63, ng = tid >> 6;    // ng 0..7, 2 nodes per thread
    float hreg[2];
    {
        float a[2] = {0.f, 0.f};
#pragma unroll 8
        for (int k = 0; k < 64; k++) {
            float wv = sWa[k * 64 + col];
            a[0] += sIn[ng * 64 + k] * wv;
            a[1] += sIn[(ng + 8) * 64 + k] * wv;
        }
        float bb = __ldg(b2 + col);
        hreg[0] = fmaxf(a[0] + bb, 0.f);
        hreg[1] = fmaxf(a[1] + bb, 0.f);
    }
    __syncthreads();

    // ---- stage C: P,Q = h2 @ Wm1 halves ----
    sIn[ng * 64 + col]       = hreg[0];
    sIn[(ng + 8) * 64 + col] = hreg[1];
    for (int i = tid; i < 4096; i += 512) { sWa[i] = Wm1[i]; sWb[i] = Wm1[4096 + i]; }
    __syncthreads();
    float p[2] = {0.f, 0.f}, q[2] = {0.f, 0.f};
#pragma unroll 8
    for (int k = 0; k < 64; k++) {
        float wa = sWa[k * 64 + col];
        float wb = sWb[k * 64 + col];
        float x0 = sIn[ng * 64 + k];
        float x1 = sIn[(ng + 8) * 64 + k];
        p[0] += x0 * wa; q[0] += x0 * wb;
        p[1] += x1 * wa; q[1] += x1 * wb;
    }
    float bmv = __ldg(bm1 + col);
#pragma unroll
    for (int m = 0; m < 2; m++) {
        size_t o = (size_t)(nb + ng + 8 * m) * 64 + col;
        g_P[o] = p[m] + bmv;
        g_Q[o] = q[m];
    }
}

// -------- edge epilogue: out[e] = relu(P[s]+Q[d]+ea@Wea) @ Wm2 + bm2 --------
// 16 lanes per edge, 2-edge unroll for memory-level parallelism
__global__ void k_edge(const int* __restrict__ src, const int* __restrict__ dst,
                       const float* __restrict__ ea,
                       const float* __restrict__ Wm1,
                       const float* __restrict__ Wm2, const float* __restrict__ bm2,
                       float* __restrict__ out) {
    int l  = threadIdx.x & 15;
    int c0 = l * 4;
    float4 w0 = *reinterpret_cast<const float4*>(Wm1 + 128 * 64 + c0);
    float4 w1 = *reinterpret_cast<const float4*>(Wm1 + 129 * 64 + c0);
    float4 w2 = *reinterpret_cast<const float4*>(Wm1 + 130 * 64 + c0);
    float4 w3 = *reinterpret_cast<const float4*>(Wm1 + 131 * 64 + c0);
    float4 wo = *reinterpret_cast<const float4*>(Wm2 + c0);
    float  ob = bm2[0];

    int grp  = (blockIdx.x * blockDim.x + threadIdx.x) >> 4;
    int ngrp = (gridDim.x * blockDim.x) >> 4;
    for (int e = grp; e < NE; e += 2 * ngrp) {
        int e2 = e + ngrp;
        bool has2 = (e2 < NE);
        int s0 = src[e], d0 = dst[e];
        int s1 = has2 ? src[e2] : s0;
        int d1 = has2 ? dst[e2] : d0;
        float4 pa = *reinterpret_cast<const float4*>(g_P + (size_t)s0 * 64 + c0);
        float4 qa = *reinterpret_cast<const float4*>(g_Q + (size_t)d0 * 64 + c0);
        float4 aa = *reinterpret_cast<const float4*>(ea + (size_t)e * 4);
        float4 pb = *reinterpret_cast<const float4*>(g_P + (size_t)s1 * 64 + c0);
        float4 qb = *reinterpret_cast<const float4*>(g_Q + (size_t)d1 * 64 + c0);
        float4 ab = *reinterpret_cast<const float4*>(ea + (size_t)(has2 ? e2 : e) * 4);

        float z0 = pa.x + qa.x + aa.x * w0.x + aa.y * w1.x + aa.z * w2.x + aa.w * w3.x;
        float z1 = pa.y + qa.y + aa.x * w0.y + aa.y * w1.y + aa.z * w2.y + aa.w * w3.y;
        float z2 = pa.z + qa.z + aa.x * w0.z + aa.y * w1.z + aa.z * w2.z + aa.w * w3.z;
        float z3 = pa.w + qa.w + aa.x * w0.w + aa.y * w1.w + aa.z * w2.w + aa.w * w3.w;
        z0 = fmaxf(z0, 0.f); z1 = fmaxf(z1, 0.f); z2 = fmaxf(z2, 0.f); z3 = fmaxf(z3, 0.f);
        float partA = z0 * wo.x + z1 * wo.y + z2 * wo.z + z3 * wo.w;

        float y0 = pb.x + qb.x + ab.x * w0.x + ab.y * w1.x + ab.z * w2.x + ab.w * w3.x;
        float y1 = pb.y + qb.y + ab.x * w0.y + ab.y * w1.y + ab.z * w2.y + ab.w * w3.y;
        float y2 = pb.z + qb.z + ab.x * w0.z + ab.y * w1.z + ab.z * w2.z + ab.w * w3.z;
        float y3 = pb.w + qb.w + ab.x * w0.w + ab.y * w1.w + ab.z * w2.w + ab.w * w3.w;
        y0 = fmaxf(y0, 0.f); y1 = fmaxf(y1, 0.f); y2 = fmaxf(y2, 0.f); y3 = fmaxf(y3, 0.f);
        float partB = y0 * wo.x + y1 * wo.y + y2 * wo.z + y3 * wo.w;

#pragma unroll
        for (int off = 8; off >= 1; off >>= 1) {
            partA += __shfl_down_sync(0xffffffffu, partA, off, 16);
            partB += __shfl_down_sync(0xffffffffu, partB, off, 16);
        }
        if (l == 0) {
            out[e] = partA + ob;
            if (has2) out[e2] = partB + ob;
        }
    }
}

extern "C" void kernel_launch(void* const* d_in, const int* in_sizes, int n_in,
                              void* d_out, int out_size) {
    const float* x   = (const float*)d_in[0];
    const int*   ei  = (const int*)  d_in[1];   // [2, NE] int32
    const float* ea  = (const float*)d_in[2];
    const float* W1  = (const float*)d_in[3];
    const float* b1  = (const float*)d_in[4];
    const float* W2  = (const float*)d_in[5];
    const float* b2  = (const float*)d_in[6];
    const float* Wm1 = (const float*)d_in[7];
    const float* bm1 = (const float*)d_in[8];
    const float* Wm2 = (const float*)d_in[9];
    const float* bm2 = (const float*)d_in[10];
    float* out = (float*)d_out;

    const int* src = ei;
    const int* dst = ei + NE;

    const int TB = 256;
    int nn_blk  = (NN + TB - 1) / TB;
    int ne_blk  = (NE + TB - 1) / TB;
    int agg_blk = (NN + 7) / 8;                  // 8 warps (nodes) per block

    // CSR build + norm
    k_zero_cnt<<<nn_blk, TB>>>();
    k_hist<<<ne_blk, TB>>>(dst);
    k_scan1<<<NB, SCAN_B>>>();
    k_scan3<<<NB, SCAN_B>>>();
    k_place<<<ne_blk, TB>>>(src, dst);

    // layer 1 (fused agg + dense)
    k_aggx_h1<<<agg_blk, TB>>>(x, W1, b1);

    // layer 2 + P,Q in one kernel (tmp & h2 never materialized)
    k_agg_dense2<<<NN / 16, 512>>>(W2, b2, Wm1, bm1);

    // edge epilogue
    k_edge<<<1184, TB>>>(src, dst, ea, Wm1, Wm2, bm2, out);
}

// round 8
// speedup vs baseline: 1.1144x; 1.1144x over previous
#include <cuda_runtime.h>
#include <cuda_fp16.h>

#define NN 100000
#define NE 3200000
#define H  64
#define SCAN_B 1024
#define NB ((NN + SCAN_B - 1) / SCAN_B)   // 98

// -------- device scratch (no allocations allowed) --------
__device__ int    g_cnt[NN];
__device__ int    g_row[NN + 1];
__device__ int    g_pos[NN];
__device__ float  g_dis[NN];
__device__ int    g_bsum[NB];
__device__ int2   g_e[NE];         // CSR slot: (src, bitcast weight)
__device__ float  g_h [NN * H];    // h1 node features (fp32)
__device__ __half g_Ph[NN * H];    // fp16: h2 @ Wm1[0:64] + bm1
__device__ __half g_Qh[NN * H];    // fp16: h2 @ Wm1[64:128]

// -------- CSR build --------
__global__ void k_zero_cnt() {
    int i = blockIdx.x * blockDim.x + threadIdx.x;
    if (i < NN) g_cnt[i] = 0;
}

__global__ void k_hist(const int* __restrict__ dst) {
    int e = blockIdx.x * blockDim.x + threadIdx.x;
    if (e < NE) atomicAdd(&g_cnt[dst[e]], 1);
}

// pass 1: per-block scan, local exclusive into g_row, block sum out
__global__ void k_scan1() {
    __shared__ int ss[SCAN_B];
    int tid = threadIdx.x;
    int i = blockIdx.x * SCAN_B + tid;
    int v = (i < NN) ? g_cnt[i] : 0;
    ss[tid] = v;
    __syncthreads();
#pragma unroll
    for (int off = 1; off < SCAN_B; off <<= 1) {
        int t = (tid >= off) ? ss[tid - off] : 0;
        __syncthreads();
        ss[tid] += t;
        __syncthreads();
    }
    if (i < NN) g_row[i] = ss[tid] - v;
    if (tid == SCAN_B - 1) g_bsum[blockIdx.x] = ss[tid];
}

// pass 2: each block reduces preceding block sums, adds offset, fuses dis
__global__ void k_scan3() {
    __shared__ int ss[128];
    int tid = threadIdx.x;
    if (tid < 128) ss[tid] = (tid < NB && tid < blockIdx.x) ? g_bsum[tid] : 0;
    __syncthreads();
#pragma unroll
    for (int off = 64; off >= 1; off >>= 1) {
        if (tid < off) ss[tid] += ss[tid + off];
        __syncthreads();
    }
    int base = ss[0];
    int i = blockIdx.x * SCAN_B + tid;
    if (i < NN) {
        int r = g_row[i] + base;
        g_row[i] = r;
        g_pos[i] = r;
        g_dis[i] = rsqrtf((float)(g_cnt[i] + 1));   // +1 self-loop
    }
    if (i == 0) g_row[NN] = NE;
}

__global__ void k_place(const int* __restrict__ src, const int* __restrict__ dst) {
    int e = blockIdx.x * blockDim.x + threadIdx.x;
    if (e >= NE) return;
    int s = src[e], d = dst[e];
    int idx = atomicAdd(&g_pos[d], 1);
    int2 ev; ev.x = s; ev.y = __float_as_int(g_dis[s] * g_dis[d]);
    g_e[idx] = ev;                       // single 8B store
}

// -------- fused layer 1: warp per node --------
__global__ void k_aggx_h1(const float* __restrict__ x,
                          const float* __restrict__ W1, const float* __restrict__ b1) {
    int w = (blockIdx.x * blockDim.x + threadIdx.x) >> 5;
    if (w >= NN) return;
    int lane = threadIdx.x & 31;
    int r0 = g_row[w], r1 = g_row[w + 1];
    float ax = 0.f, ay = 0.f, az = 0.f, aw = 0.f;
#pragma unroll 4
    for (int r = r0 + lane; r < r1; r += 32) {
        int2 ev = g_e[r];
        float ww = __int_as_float(ev.y);
        float4 xv = *reinterpret_cast<const float4*>(x + (size_t)ev.x * 4);
        ax += xv.x * ww; ay += xv.y * ww; az += xv.z * ww; aw += xv.w * ww;
    }
    if (lane == 0) {                     // self-loop
        float dd = g_dis[w]; dd *= dd;
        float4 xv = *reinterpret_cast<const float4*>(x + (size_t)w * 4);
        ax += dd * xv.x; ay += dd * xv.y; az += dd * xv.z; aw += dd * xv.w;
    }
#pragma unroll
    for (int off = 16; off >= 1; off >>= 1) {
        ax += __shfl_xor_sync(0xffffffffu, ax, off);
        ay += __shfl_xor_sync(0xffffffffu, ay, off);
        az += __shfl_xor_sync(0xffffffffu, az, off);
        aw += __shfl_xor_sync(0xffffffffu, aw, off);
    }
    size_t o = (size_t)w * H;
#pragma unroll
    for (int half = 0; half < 2; half++) {
        int c = lane + half * 32;
        float s = ax * __ldg(W1 + c) + ay * __ldg(W1 + 64 + c)
                + az * __ldg(W1 + 128 + c) + aw * __ldg(W1 + 192 + c) + __ldg(b1 + c);
        g_h[o + c] = fmaxf(s, 0.f);
    }
}

// -------- fused layer 2 + P,Q (fp16 out) --------
// Block: 512 thr = 16 warps = 16 nodes.
__global__ void k_agg_dense2(const float* __restrict__ W2, const float* __restrict__ b2,
                             const float* __restrict__ Wm1, const float* __restrict__ bm1) {
    __shared__ float sbuf[9216];      // 4096 Wa | 4096 Wb | 1024 node tile
    float* sWa = sbuf;
    float* sWb = sbuf + 4096;
    float* sIn = sbuf + 8192;
    int tid  = threadIdx.x;
    int nb   = blockIdx.x * 16;
    int wid  = tid >> 5, lane = tid & 31;

    // stage A: warp-per-node aggregation of h1, 4-edge unrolled
    {
        int node = nb + wid;
        const float2* hp = reinterpret_cast<const float2*>(g_h);
        int r = g_row[node], r1 = g_row[node + 1];
        float a0 = 0.f, a1 = 0.f;
        for (; r + 3 < r1; r += 4) {
            int2 e0 = g_e[r],     e1 = g_e[r + 1], e2 = g_e[r + 2], e3 = g_e[r + 3];
            float2 v0 = hp[(size_t)e0.x * 32 + lane];
            float2 v1 = hp[(size_t)e1.x * 32 + lane];
            float2 v2 = hp[(size_t)e2.x * 32 + lane];
            float2 v3 = hp[(size_t)e3.x * 32 + lane];
            float w0 = __int_as_float(e0.y), w1 = __int_as_float(e1.y);
            float w2 = __int_as_float(e2.y), w3 = __int_as_float(e3.y);
            a0 += v0.x * w0; a1 += v0.y * w0;
            a0 += v1.x * w1; a1 += v1.y * w1;
            a0 += v2.x * w2; a1 += v2.y * w2;
            a0 += v3.x * w3; a1 += v3.y * w3;
        }
        for (; r < r1; r++) {
            int2 ev = g_e[r];
            float2 v = hp[(size_t)ev.x * 32 + lane];
            float ww = __int_as_float(ev.y);
            a0 += v.x * ww; a1 += v.y * ww;
        }
        float dd = g_dis[node]; dd *= dd;
        float2 v = hp[(size_t)node * 32 + lane];
        a0 += v.x * dd; a1 += v.y * dd;
        sIn[wid * 64 + 2 * lane]     = a0;
        sIn[wid * 64 + 2 * lane + 1] = a1;
    }
    for (int i = tid; i < 4096; i += 512) sWa[i] = W2[i];
    __syncthreads();

    // stage B: h2 = relu(tmp@W2 + b2) in registers
    int col = tid & 63, ng = tid >> 6;    // ng 0..7, 2 nodes per thread
    float hreg[2];
    {
        float a[2] = {0.f, 0.f};
#pragma unroll 8
        for (int k = 0; k < 64; k++) {
            float wv = sWa[k * 64 + col];
            a[0] += sIn[ng * 64 + k] * wv;
            a[1] += sIn[(ng + 8) * 64 + k] * wv;
        }
        float bb = __ldg(b2 + col);
        hreg[0] = fmaxf(a[0] + bb, 0.f);
        hreg[1] = fmaxf(a[1] + bb, 0.f);
    }
    __syncthreads();

    // stage C: P,Q = h2 @ Wm1 halves -> fp16
    sIn[ng * 64 + col]       = hreg[0];
    sIn[(ng + 8) * 64 + col] = hreg[1];
    for (int i = tid; i < 4096; i += 512) { sWa[i] = Wm1[i]; sWb[i] = Wm1[4096 + i]; }
    __syncthreads();
    float p[2] = {0.f, 0.f}, q[2] = {0.f, 0.f};
#pragma unroll 8
    for (int k = 0; k < 64; k++) {
        float wa = sWa[k * 64 + col];
        float wb = sWb[k * 64 + col];
        float x0 = sIn[ng * 64 + k];
        float x1 = sIn[(ng + 8) * 64 + k];
        p[0] += x0 * wa; q[0] += x0 * wb;
        p[1] += x1 * wa; q[1] += x1 * wb;
    }
    float bmv = __ldg(bm1 + col);
#pragma unroll
    for (int m = 0; m < 2; m++) {
        size_t o = (size_t)(nb + ng + 8 * m) * 64 + col;
        g_Ph[o] = __float2half(p[m] + bmv);
        g_Qh[o] = __float2half(q[m]);
    }
}

// -------- edge epilogue: out[e] = relu(P[s]+Q[d]+ea@Wea) @ Wm2 + bm2 --------
// 16 lanes per edge (4 cols each), 4-edge unroll for MLP.
__global__ void k_edge(const int* __restrict__ src, const int* __restrict__ dst,
                       const float* __restrict__ ea,
                       const float* __restrict__ Wm1,
                       const float* __restrict__ Wm2, const float* __restrict__ bm2,
                       float* __restrict__ out) {
    int l  = threadIdx.x & 15;
    int c0 = l * 4;
    float4 w0 = *reinterpret_cast<const float4*>(Wm1 + 128 * 64 + c0);
    float4 w1 = *reinterpret_cast<const float4*>(Wm1 + 129 * 64 + c0);
    float4 w2 = *reinterpret_cast<const float4*>(Wm1 + 130 * 64 + c0);
    float4 w3 = *reinterpret_cast<const float4*>(Wm1 + 131 * 64 + c0);
    float4 wo = *reinterpret_cast<const float4*>(Wm2 + c0);
    float  ob = bm2[0];

    int grp  = (blockIdx.x * blockDim.x + threadIdx.x) >> 4;
    int ngrp = (gridDim.x * blockDim.x) >> 4;
    for (int e0 = grp; e0 < NE; e0 += 4 * ngrp) {
        float part[4];
        int   ee[4];
        bool  ok[4];
#pragma unroll
        for (int u = 0; u < 4; u++) {
            int e = e0 + u * ngrp;
            ok[u] = (e < NE);
            ee[u] = ok[u] ? e : e0;
            int s = src[ee[u]], d = dst[ee[u]];
            uint2 pv = *reinterpret_cast<const uint2*>(g_Ph + (size_t)s * 64 + c0);
            uint2 qv = *reinterpret_cast<const uint2*>(g_Qh + (size_t)d * 64 + c0);
            float4 a = *reinterpret_cast<const float4*>(ea + (size_t)ee[u] * 4);
            float2 p01 = __half22float2(*reinterpret_cast<__half2*>(&pv.x));
            float2 p23 = __half22float2(*reinterpret_cast<__half2*>(&pv.y));
            float2 q01 = __half22float2(*reinterpret_cast<__half2*>(&qv.x));
            float2 q23 = __half22float2(*reinterpret_cast<__half2*>(&qv.y));
            float z0 = p01.x + q01.x + a.x * w0.x + a.y * w1.x + a.z * w2.x + a.w * w3.x;
            float z1 = p01.y + q01.y + a.x * w0.y + a.y * w1.y + a.z * w2.y + a.w * w3.y;
            float z2 = p23.x + q23.x + a.x * w0.z + a.y * w1.z + a.z * w2.z + a.w * w3.z;
            float z3 = p23.y + q23.y + a.x * w0.w + a.y * w1.w + a.z * w2.w + a.w * w3.w;
            z0 = fmaxf(z0, 0.f); z1 = fmaxf(z1, 0.f); z2 = fmaxf(z2, 0.f); z3 = fmaxf(z3, 0.f);
            part[u] = z0 * wo.x + z1 * wo.y + z2 * wo.z + z3 * wo.w;
        }
#pragma unroll
        for (int off = 8; off >= 1; off >>= 1) {
#pragma unroll
            for (int u = 0; u < 4; u++)
                part[u] += __shfl_down_sync(0xffffffffu, part[u], off, 16);
        }
        if (l == 0) {
#pragma unroll
            for (int u = 0; u < 4; u++)
                if (ok[u]) out[ee[u]] = part[u] + ob;
        }
    }
}

extern "C" void kernel_launch(void* const* d_in, const int* in_sizes, int n_in,
                              void* d_out, int out_size) {
    const float* x   = (const float*)d_in[0];
    const int*   ei  = (const int*)  d_in[1];   // [2, NE] int32
    const float* ea  = (const float*)d_in[2];
    const float* W1  = (const float*)d_in[3];
    const float* b1  = (const float*)d_in[4];
    const float* W2  = (const float*)d_in[5];
    const float* b2  = (const float*)d_in[6];
    const float* Wm1 = (const float*)d_in[7];
    const float* bm1 = (const float*)d_in[8];
    const float* Wm2 = (const float*)d_in[9];
    const float* bm2 = (const float*)d_in[10];
    float* out = (float*)d_out;

    const int* src = ei;
    const int* dst = ei + NE;

    const int TB = 256;
    int nn_blk  = (NN + TB - 1) / TB;
    int ne_blk  = (NE + TB - 1) / TB;
    int agg_blk = (NN + 7) / 8;                  // 8 warps (nodes) per block

    // CSR build + norm
    k_zero_cnt<<<nn_blk, TB>>>();
    k_hist<<<ne_blk, TB>>>(dst);
    k_scan1<<<NB, SCAN_B>>>();
    k_scan3<<<NB, SCAN_B>>>();
    k_place<<<ne_blk, TB>>>(src, dst);

    // layer 1 (fused agg + dense)
    k_aggx_h1<<<agg_blk, TB>>>(x, W1, b1);

    // layer 2 + P,Q in one kernel (fp16 P/Q out)
    k_agg_dense2<<<NN / 16, 512>>>(W2, b2, Wm1, bm1);

    // edge epilogue
    k_edge<<<1184, TB>>>(src, dst, ea, Wm1, Wm2, bm2, out);
}

// round 9
// speedup vs baseline: 1.1324x; 1.0162x over previous
#include <cuda_runtime.h>
#include <cuda_fp16.h>

#define NN 100000
#define NE 3200000
#define H  64
#define SCAN_B 1024
#define NB ((NN + SCAN_B - 1) / SCAN_B)   // 98

// -------- device scratch (no allocations allowed) --------
__device__ int     g_cnt[NN];
__device__ int     g_row[NN + 1];
__device__ int     g_pos[NN];
__device__ float   g_dis[NN];
__device__ int     g_bsum[NB];
__device__ int2    g_e[NE];          // CSR slot: (src, bitcast weight)
__device__ __half2 g_h1h[NN * 32];   // h1 node features, fp16 pairs (cols 2l, 2l+1)
__device__ __half  g_Ph[NN * H];     // fp16: h2 @ Wm1[0:64] + bm1
__device__ __half  g_Qh[NN * H];     // fp16: h2 @ Wm1[64:128]

// -------- CSR build --------
__global__ void k_zero_cnt() {
    int i = blockIdx.x * blockDim.x + threadIdx.x;
    if (i < NN) g_cnt[i] = 0;
}

__global__ void k_hist(const int* __restrict__ dst) {
    int e = blockIdx.x * blockDim.x + threadIdx.x;
    if (e < NE) atomicAdd(&g_cnt[dst[e]], 1);
}

// pass 1: per-block scan, local exclusive into g_row, block sum out
__global__ void k_scan1() {
    __shared__ int ss[SCAN_B];
    int tid = threadIdx.x;
    int i = blockIdx.x * SCAN_B + tid;
    int v = (i < NN) ? g_cnt[i] : 0;
    ss[tid] = v;
    __syncthreads();
#pragma unroll
    for (int off = 1; off < SCAN_B; off <<= 1) {
        int t = (tid >= off) ? ss[tid - off] : 0;
        __syncthreads();
        ss[tid] += t;
        __syncthreads();
    }
    if (i < NN) g_row[i] = ss[tid] - v;
    if (tid == SCAN_B - 1) g_bsum[blockIdx.x] = ss[tid];
}

// pass 2: each block reduces preceding block sums, adds offset, fuses dis
__global__ void k_scan3() {
    __shared__ int ss[128];
    int tid = threadIdx.x;
    if (tid < 128) ss[tid] = (tid < NB && tid < blockIdx.x) ? g_bsum[tid] : 0;
    __syncthreads();
#pragma unroll
    for (int off = 64; off >= 1; off >>= 1) {
        if (tid < off) ss[tid] += ss[tid + off];
        __syncthreads();
    }
    int base = ss[0];
    int i = blockIdx.x * SCAN_B + tid;
    if (i < NN) {
        int r = g_row[i] + base;
        g_row[i] = r;
        g_pos[i] = r;
        g_dis[i] = rsqrtf((float)(g_cnt[i] + 1));   // +1 self-loop
    }
    if (i == 0) g_row[NN] = NE;
}

__global__ void k_place(const int* __restrict__ src, const int* __restrict__ dst) {
    int e = blockIdx.x * blockDim.x + threadIdx.x;
    if (e >= NE) return;
    int s = src[e], d = dst[e];
    int idx = atomicAdd(&g_pos[d], 1);
    int2 ev; ev.x = s; ev.y = __float_as_int(g_dis[s] * g_dis[d]);
    g_e[idx] = ev;                       // single 8B store
}

// -------- fused layer 1: warp per node; h1 out in fp16 pairs --------
__global__ void k_aggx_h1(const float* __restrict__ x,
                          const float* __restrict__ W1, const float* __restrict__ b1) {
    int w = (blockIdx.x * blockDim.x + threadIdx.x) >> 5;
    if (w >= NN) return;
    int lane = threadIdx.x & 31;
    int r0 = g_row[w], r1 = g_row[w + 1];
    float ax = 0.f, ay = 0.f, az = 0.f, aw = 0.f;
#pragma unroll 4
    for (int r = r0 + lane; r < r1; r += 32) {
        int2 ev = g_e[r];
        float ww = __int_as_float(ev.y);
        float4 xv = *reinterpret_cast<const float4*>(x + (size_t)ev.x * 4);
        ax += xv.x * ww; ay += xv.y * ww; az += xv.z * ww; aw += xv.w * ww;
    }
    if (lane == 0) {                     // self-loop
        float dd = g_dis[w]; dd *= dd;
        float4 xv = *reinterpret_cast<const float4*>(x + (size_t)w * 4);
        ax += dd * xv.x; ay += dd * xv.y; az += dd * xv.z; aw += dd * xv.w;
    }
#pragma unroll
    for (int off = 16; off >= 1; off >>= 1) {
        ax += __shfl_xor_sync(0xffffffffu, ax, off);
        ay += __shfl_xor_sync(0xffffffffu, ay, off);
        az += __shfl_xor_sync(0xffffffffu, az, off);
        aw += __shfl_xor_sync(0xffffffffu, aw, off);
    }
    // lane computes adjacent columns 2*lane, 2*lane+1 -> one __half2 store
    int c0 = 2 * lane, c1 = 2 * lane + 1;
    float s0 = ax * __ldg(W1 + c0) + ay * __ldg(W1 + 64 + c0)
             + az * __ldg(W1 + 128 + c0) + aw * __ldg(W1 + 192 + c0) + __ldg(b1 + c0);
    float s1 = ax * __ldg(W1 + c1) + ay * __ldg(W1 + 64 + c1)
             + az * __ldg(W1 + 128 + c1) + aw * __ldg(W1 + 192 + c1) + __ldg(b1 + c1);
    g_h1h[(size_t)w * 32 + lane] = __floats2half2_rn(fmaxf(s0, 0.f), fmaxf(s1, 0.f));
}

// -------- fused layer 2 + P,Q (fp16 in/out) --------
// Block: 512 thr = 16 warps = 16 nodes.
__global__ void k_agg_dense2(const float* __restrict__ W2, const float* __restrict__ b2,
                             const float* __restrict__ Wm1, const float* __restrict__ bm1) {
    __shared__ float sbuf[9216];      // 4096 Wa | 4096 Wb | 1024 node tile
    float* sWa = sbuf;
    float* sWb = sbuf + 4096;
    float* sIn = sbuf + 8192;
    int tid  = threadIdx.x;
    int nb   = blockIdx.x * 16;
    int wid  = tid >> 5, lane = tid & 31;

    // stage A: warp-per-node aggregation of fp16 h1, 4-edge unrolled
    {
        int node = nb + wid;
        int r = g_row[node], r1 = g_row[node + 1];
        float a0 = 0.f, a1 = 0.f;
        for (; r + 3 < r1; r += 4) {
            int2 e0 = g_e[r],     e1 = g_e[r + 1], e2 = g_e[r + 2], e3 = g_e[r + 3];
            float2 v0 = __half22float2(g_h1h[(size_t)e0.x * 32 + lane]);
            float2 v1 = __half22float2(g_h1h[(size_t)e1.x * 32 + lane]);
            float2 v2 = __half22float2(g_h1h[(size_t)e2.x * 32 + lane]);
            float2 v3 = __half22float2(g_h1h[(size_t)e3.x * 32 + lane]);
            float w0 = __int_as_float(e0.y), w1 = __int_as_float(e1.y);
            float w2 = __int_as_float(e2.y), w3 = __int_as_float(e3.y);
            a0 += v0.x * w0; a1 += v0.y * w0;
            a0 += v1.x * w1; a1 += v1.y * w1;
            a0 += v2.x * w2; a1 += v2.y * w2;
            a0 += v3.x * w3; a1 += v3.y * w3;
        }
        for (; r < r1; r++) {
            int2 ev = g_e[r];
            float2 v = __half22float2(g_h1h[(size_t)ev.x * 32 + lane]);
            float ww = __int_as_float(ev.y);
            a0 += v.x * ww; a1 += v.y * ww;
        }
        float dd = g_dis[node]; dd *= dd;
        float2 v = __half22float2(g_h1h[(size_t)node * 32 + lane]);
        a0 += v.x * dd; a1 += v.y * dd;
        sIn[wid * 64 + 2 * lane]     = a0;
        sIn[wid * 64 + 2 * lane + 1] = a1;
    }
    for (int i = tid; i < 4096; i += 512) sWa[i] = W2[i];
    __syncthreads();

    // stage B: h2 = relu(tmp@W2 + b2) in registers
    int col = tid & 63, ng = tid >> 6;    // ng 0..7, 2 nodes per thread
    float hreg[2];
    {
        float a[2] = {0.f, 0.f};
#pragma unroll 8
        for (int k = 0; k < 64; k++) {
            float wv = sWa[k * 64 + col];
            a[0] += sIn[ng * 64 + k] * wv;
            a[1] += sIn[(ng + 8) * 64 + k] * wv;
        }
        float bb = __ldg(b2 + col);
        hreg[0] = fmaxf(a[0] + bb, 0.f);
        hreg[1] = fmaxf(a[1] + bb, 0.f);
    }
    __syncthreads();

    // stage C: P,Q = h2 @ Wm1 halves -> fp16
    sIn[ng * 64 + col]       = hreg[0];
    sIn[(ng + 8) * 64 + col] = hreg[1];
    for (int i = tid; i < 4096; i += 512) { sWa[i] = Wm1[i]; sWb[i] = Wm1[4096 + i]; }
    __syncthreads();
    float p[2] = {0.f, 0.f}, q[2] = {0.f, 0.f};
#pragma unroll 8
    for (int k = 0; k < 64; k++) {
        float wa = sWa[k * 64 + col];
        float wb = sWb[k * 64 + col];
        float x0 = sIn[ng * 64 + k];
        float x1 = sIn[(ng + 8) * 64 + k];
        p[0] += x0 * wa; q[0] += x0 * wb;
        p[1] += x1 * wa; q[1] += x1 * wb;
    }
    float bmv = __ldg(bm1 + col);
#pragma unroll
    for (int m = 0; m < 2; m++) {
        size_t o = (size_t)(nb + ng + 8 * m) * 64 + col;
        g_Ph[o] = __float2half(p[m] + bmv);
        g_Qh[o] = __float2half(q[m]);
    }
}

// -------- edge epilogue: out[e] = relu(P[s]+Q[d]+ea@Wea) @ Wm2 + bm2 --------
// 16 lanes per edge (4 cols each), 4-edge unroll for MLP.
__global__ void k_edge(const int* __restrict__ src, const int* __restrict__ dst,
                       const float* __restrict__ ea,
                       const float* __restrict__ Wm1,
                       const float* __restrict__ Wm2, const float* __restrict__ bm2,
                       float* __restrict__ out) {
    int l  = threadIdx.x & 15;
    int c0 = l * 4;
    float4 w0 = *reinterpret_cast<const float4*>(Wm1 + 128 * 64 + c0);
    float4 w1 = *reinterpret_cast<const float4*>(Wm1 + 129 * 64 + c0);
    float4 w2 = *reinterpret_cast<const float4*>(Wm1 + 130 * 64 + c0);
    float4 w3 = *reinterpret_cast<const float4*>(Wm1 + 131 * 64 + c0);
    float4 wo = *reinterpret_cast<const float4*>(Wm2 + c0);
    float  ob = bm2[0];

    int grp  = (blockIdx.x * blockDim.x + threadIdx.x) >> 4;
    int ngrp = (gridDim.x * blockDim.x) >> 4;
    for (int e0 = grp; e0 < NE; e0 += 4 * ngrp) {
        float part[4];
        int   ee[4];
        bool  ok[4];
#pragma unroll
        for (int u = 0; u < 4; u++) {
            int e = e0 + u * ngrp;
            ok[u] = (e < NE);
            ee[u] = ok[u] ? e : e0;
            int s = src[ee[u]], d = dst[ee[u]];
            uint2 pv = *reinterpret_cast<const uint2*>(g_Ph + (size_t)s * 64 + c0);
            uint2 qv = *reinterpret_cast<const uint2*>(g_Qh + (size_t)d * 64 + c0);
            float4 a = *reinterpret_cast<const float4*>(ea + (size_t)ee[u] * 4);
            float2 p01 = __half22float2(*reinterpret_cast<__half2*>(&pv.x));
            float2 p23 = __half22float2(*reinterpret_cast<__half2*>(&pv.y));
            float2 q01 = __half22float2(*reinterpret_cast<__half2*>(&qv.x));
            float2 q23 = __half22float2(*reinterpret_cast<__half2*>(&qv.y));
            float z0 = p01.x + q01.x + a.x * w0.x + a.y * w1.x + a.z * w2.x + a.w * w3.x;
            float z1 = p01.y + q01.y + a.x * w0.y + a.y * w1.y + a.z * w2.y + a.w * w3.y;
            float z2 = p23.x + q23.x + a.x * w0.z + a.y * w1.z + a.z * w2.z + a.w * w3.z;
            float z3 = p23.y + q23.y + a.x * w0.w + a.y * w1.w + a.z * w2.w + a.w * w3.w;
            z0 = fmaxf(z0, 0.f); z1 = fmaxf(z1, 0.f); z2 = fmaxf(z2, 0.f); z3 = fmaxf(z3, 0.f);
            part[u] = z0 * wo.x + z1 * wo.y + z2 * wo.z + z3 * wo.w;
        }
#pragma unroll
        for (int off = 8; off >= 1; off >>= 1) {
#pragma unroll
            for (int u = 0; u < 4; u++)
                part[u] += __shfl_down_sync(0xffffffffu, part[u], off, 16);
        }
        if (l == 0) {
#pragma unroll
            for (int u = 0; u < 4; u++)
                if (ok[u]) out[ee[u]] = part[u] + ob;
        }
    }
}

extern "C" void kernel_launch(void* const* d_in, const int* in_sizes, int n_in,
                              void* d_out, int out_size) {
    const float* x   = (const float*)d_in[0];
    const int*   ei  = (const int*)  d_in[1];   // [2, NE] int32
    const float* ea  = (const float*)d_in[2];
    const float* W1  = (const float*)d_in[3];
    const float* b1  = (const float*)d_in[4];
    const float* W2  = (const float*)d_in[5];
    const float* b2  = (const float*)d_in[6];
    const float* Wm1 = (const float*)d_in[7];
    const float* bm1 = (const float*)d_in[8];
    const float* Wm2 = (const float*)d_in[9];
    const float* bm2 = (const float*)d_in[10];
    float* out = (float*)d_out;

    const int* src = ei;
    const int* dst = ei + NE;

    const int TB = 256;
    int nn_blk  = (NN + TB - 1) / TB;
    int ne_blk  = (NE + TB - 1) / TB;
    int agg_blk = (NN + 7) / 8;                  // 8 warps (nodes) per block

    // CSR build + norm
    k_zero_cnt<<<nn_blk, TB>>>();
    k_hist<<<ne_blk, TB>>>(dst);
    k_scan1<<<NB, SCAN_B>>>();
    k_scan3<<<NB, SCAN_B>>>();
    k_place<<<ne_blk, TB>>>(src, dst);

    // layer 1 (fused agg + dense, fp16 h1 out)
    k_aggx_h1<<<agg_blk, TB>>>(x, W1, b1);

    // layer 2 + P,Q in one kernel (fp16 in/out)
    k_agg_dense2<<<NN / 16, 512>>>(W2, b2, Wm1, bm1);

    // edge epilogue
    k_edge<<<1184, TB>>>(src, dst, ea, Wm1, Wm2, bm2, out);
}